// round 4
// baseline (speedup 1.0000x reference)
#include <cuda_runtime.h>
#include <cstdint>

#define NN 50000
#define EE 800000
#define RR 8
#define HD 128
#define NG 2            // graphs

#define GM 128
#define KC 32
#define SA_STRIDE 36    // A chunk row stride (words): conflict-free frags+stores
#define SB_STRIDE 132   // B chunk row stride
#define MBLK ((NN + GM - 1) / GM)

// ---------------- scratch (device globals; no allocation allowed) ----------
__device__ float g_xt[(size_t)NG * RR * NN * HD];  // 409.6 MB xt[g][r][n][o]
__device__ float g_acc[(size_t)NG * NN * HD];      // unnormalized aggregation
__device__ float g_denom[NG * NN];                 // sum of exp per dst
__device__ float g_wq[NG * RR * HD];               // W_r @ q
__device__ float g_wk[NG * RR * HD];               // W_r @ k
__device__ float g_qi[NG * NN * RR];               // x[n] . wq[r]
__device__ float g_kj[NG * NN * RR];               // x[n] . wk[r]

__device__ __forceinline__ uint32_t f2tf32(float f) {
    uint32_t u;
    asm("cvt.rna.tf32.f32 %0, %1;" : "=r"(u) : "f"(f));
    return u;
}

// ---------------- zero acc + denom -----------------------------------------
__global__ void zero_kernel() {
    int i = blockIdx.x * blockDim.x + threadIdx.x;
    int stride = gridDim.x * blockDim.x;
    float4 z = make_float4(0.f, 0.f, 0.f, 0.f);
    float4* a4 = (float4*)g_acc;
    const int na4 = NG * NN * HD / 4;
    for (int j = i; j < na4; j += stride) a4[j] = z;
    for (int j = i; j < NG * NN; j += stride) g_denom[j] = 0.f;
}

// ---------------- Wq[r] = W_r @ q, Wk[r] = W_r @ k (both graphs) ------------
__global__ void wqwk_kernel(const float* __restrict__ W1, const float* __restrict__ q1,
                            const float* __restrict__ k1,
                            const float* __restrict__ W2, const float* __restrict__ q2,
                            const float* __restrict__ k2) {
    int graph = blockIdx.y;
    const float* W = graph ? W2 : W1;
    const float* q = graph ? q2 : q1;
    const float* k = graph ? k2 : k1;
    int w = (blockIdx.x * blockDim.x + threadIdx.x) >> 5;  // 0..1023 = r*128+d
    int lane = threadIdx.x & 31;
    if (w >= RR * HD) return;
    const float* row = W + (size_t)w * HD;
    float sq = 0.f, sk = 0.f;
#pragma unroll
    for (int j = lane; j < HD; j += 32) {
        float wv = row[j];
        sq += wv * q[j];
        sk += wv * k[j];
    }
#pragma unroll
    for (int o = 16; o; o >>= 1) {
        sq += __shfl_xor_sync(0xffffffffu, sq, o);
        sk += __shfl_xor_sync(0xffffffffu, sk, o);
    }
    if (lane == 0) {
        g_wq[graph * RR * HD + w] = sq;
        g_wk[graph * RR * HD + w] = sk;
    }
}

// ---------------- per-node logit tables: qi[n][r], kj[n][r] -----------------
__global__ void table_kernel(const float* __restrict__ x1,
                             const float* __restrict__ x2) {
    int graph = blockIdx.y;
    const float* x = graph ? x2 : x1;
    int n = (blockIdx.x * blockDim.x + threadIdx.x) >> 5;
    if (n >= NN) return;
    int lane = threadIdx.x & 31;
    float4 xv = ((const float4*)x)[(size_t)n * 32 + lane];
    const float4* wq4 = (const float4*)(g_wq + graph * RR * HD);
    const float4* wk4 = (const float4*)(g_wk + graph * RR * HD);
#pragma unroll
    for (int r = 0; r < RR; r++) {
        float4 wq = wq4[r * 32 + lane];
        float4 wk = wk4[r * 32 + lane];
        float sq = xv.x * wq.x + xv.y * wq.y + xv.z * wq.z + xv.w * wq.w;
        float sk = xv.x * wk.x + xv.y * wk.y + xv.z * wk.z + xv.w * wk.w;
#pragma unroll
        for (int o = 16; o; o >>= 1) {
            sq += __shfl_xor_sync(0xffffffffu, sq, o);
            sk += __shfl_xor_sync(0xffffffffu, sk, o);
        }
        if (lane == 0) {
            g_qi[(graph * NN + n) * RR + r] = sq;
            g_kj[(graph * NN + n) * RR + r] = sk;
        }
    }
}

// ---------------- xt[g][r] = x @ W_r  (tf32 mma.sync) -----------------------
// One CTA per (m-tile, relation, graph). K chunked at 32, single smem buffer
// (~35KB) -> 3 CTAs/SM for latency hiding.
__global__ __launch_bounds__(256, 3)
void xt_gemm(const float* __restrict__ x1, const float* __restrict__ x2,
             const float* __restrict__ W1, const float* __restrict__ W2) {
    __shared__ uint32_t As[GM * SA_STRIDE];
    __shared__ uint32_t Bs[KC * SB_STRIDE];
    int graph = blockIdx.z;
    int r = blockIdx.y;
    const float* x = graph ? x2 : x1;
    const float* W = (graph ? W2 : W1) + (size_t)r * HD * HD;
    int m0 = blockIdx.x * GM;
    int tid = threadIdx.x;
    int wid = tid >> 5, lane = tid & 31;
    int warpM = wid >> 1;    // 0..3 -> 32-row slab
    int warpN = wid & 1;     // 0..1 -> 64-col slab
    int g = lane >> 2, t = lane & 3;

    float acc[2][8][4];
#pragma unroll
    for (int mt = 0; mt < 2; mt++)
#pragma unroll
        for (int nt = 0; nt < 8; nt++)
#pragma unroll
            for (int c = 0; c < 4; c++) acc[mt][nt][c] = 0.f;

    for (int k0 = 0; k0 < HD; k0 += KC) {
        __syncthreads();
        // A chunk: 128 rows x 8 float4 (K=32)
#pragma unroll
        for (int i = 0; i < 4; i++) {
            int idx = tid + i * 256;
            int row = idx >> 3, c4 = idx & 7;
            int gm = m0 + row;
            float4 v = make_float4(0.f, 0.f, 0.f, 0.f);
            if (gm < NN) v = ((const float4*)x)[(size_t)gm * 32 + (k0 >> 2) + c4];
            uint4 u = make_uint4(f2tf32(v.x), f2tf32(v.y), f2tf32(v.z), f2tf32(v.w));
            *(uint4*)&As[row * SA_STRIDE + c4 * 4] = u;
        }
        // B chunk: 32 rows x 32 float4 (N=128)
#pragma unroll
        for (int i = 0; i < 4; i++) {
            int idx = tid + i * 256;
            int row = idx >> 5, c4 = idx & 31;
            float4 v = ((const float4*)W)[(size_t)(k0 + row) * 32 + c4];
            uint4 u = make_uint4(f2tf32(v.x), f2tf32(v.y), f2tf32(v.z), f2tf32(v.w));
            *(uint4*)&Bs[row * SB_STRIDE + c4 * 4] = u;
        }
        __syncthreads();
#pragma unroll
        for (int kk = 0; kk < KC; kk += 8) {
            uint32_t a[2][4];
#pragma unroll
            for (int mt = 0; mt < 2; mt++) {
                int rb = warpM * 32 + mt * 16 + g;
                a[mt][0] = As[rb * SA_STRIDE + kk + t];
                a[mt][1] = As[(rb + 8) * SA_STRIDE + kk + t];
                a[mt][2] = As[rb * SA_STRIDE + kk + t + 4];
                a[mt][3] = As[(rb + 8) * SA_STRIDE + kk + t + 4];
            }
#pragma unroll
            for (int nt = 0; nt < 8; nt++) {
                int col = warpN * 64 + nt * 8 + g;
                uint32_t b0 = Bs[(kk + t) * SB_STRIDE + col];
                uint32_t b1 = Bs[(kk + t + 4) * SB_STRIDE + col];
#pragma unroll
                for (int mt = 0; mt < 2; mt++) {
                    asm volatile(
                        "mma.sync.aligned.m16n8k8.row.col.f32.tf32.tf32.f32 "
                        "{%0,%1,%2,%3}, {%4,%5,%6,%7}, {%8,%9}, {%0,%1,%2,%3};"
                        : "+f"(acc[mt][nt][0]), "+f"(acc[mt][nt][1]),
                          "+f"(acc[mt][nt][2]), "+f"(acc[mt][nt][3])
                        : "r"(a[mt][0]), "r"(a[mt][1]), "r"(a[mt][2]), "r"(a[mt][3]),
                          "r"(b0), "r"(b1));
                }
            }
        }
    }

    // store to xt[graph][r]
    float* xt = g_xt + ((size_t)(graph * RR + r) * NN) * HD;
#pragma unroll
    for (int mt = 0; mt < 2; mt++) {
        int row0 = m0 + warpM * 32 + mt * 16 + g;
#pragma unroll
        for (int nt = 0; nt < 8; nt++) {
            int col = warpN * 64 + nt * 8 + t * 2;
            if (row0 < NN) {
                float2 v = make_float2(acc[mt][nt][0], acc[mt][nt][1]);
                *(float2*)&xt[(size_t)row0 * HD + col] = v;
            }
            if (row0 + 8 < NN) {
                float2 v = make_float2(acc[mt][nt][2], acc[mt][nt][3]);
                *(float2*)&xt[(size_t)(row0 + 8) * HD + col] = v;
            }
        }
    }
}

// ---------------- single edge pass: denom += ex; acc[dst] += ex*xt[r,src] ---
__global__ void edge_kernel(const int* __restrict__ ei1, const int* __restrict__ et1,
                            const int* __restrict__ ei2, const int* __restrict__ et2) {
    int graph = blockIdx.y;
    const int* ei = graph ? ei2 : ei1;
    const int* et = graph ? et2 : et1;
    int e = (blockIdx.x * blockDim.x + threadIdx.x) >> 5;
    if (e >= EE) return;
    int lane = threadIdx.x & 31;
    int src = __ldg(ei + e);
    int dst = __ldg(ei + EE + e);
    int r = __ldg(et + e);
    float al = g_qi[(graph * NN + dst) * RR + r] + g_kj[(graph * NN + src) * RR + r];
    al = al > 0.f ? al : 0.2f * al;           // leaky_relu
    float ex = __expf(al);                    // alpha ~ O(1): no max-shift
    if (lane == 0) atomicAdd(&g_denom[graph * NN + dst], ex);
    float4 v = ((const float4*)g_xt)[((size_t)(graph * RR + r) * NN + src) * 32 + lane];
    v.x *= ex; v.y *= ex; v.z *= ex; v.w *= ex;
    float* p = &g_acc[((size_t)(graph * NN) + dst) * HD + lane * 4];
    asm volatile("red.global.add.v4.f32 [%0], {%1,%2,%3,%4};"
                 :: "l"(p), "f"(v.x), "f"(v.y), "f"(v.z), "f"(v.w)
                 : "memory");
}

// ---------------- out = relu(acc/denom + b) ---------------------------------
__global__ void epilogue_kernel(const float* __restrict__ b1,
                                const float* __restrict__ b2,
                                float* __restrict__ out) {
    int graph = blockIdx.y;
    const float* bias = graph ? b2 : b1;
    int i = blockIdx.x * blockDim.x + threadIdx.x;   // over NN*32 float4s
    if (i >= NN * 32) return;
    int n = i >> 5, c4 = i & 31;
    float inv = 1.0f / (g_denom[graph * NN + n] + 1e-16f);
    float4 v = ((const float4*)g_acc)[(size_t)graph * NN * 32 + i];
    float4 bb = ((const float4*)bias)[c4];
    v.x = fmaxf(v.x * inv + bb.x, 0.f);
    v.y = fmaxf(v.y * inv + bb.y, 0.f);
    v.z = fmaxf(v.z * inv + bb.z, 0.f);
    v.w = fmaxf(v.w * inv + bb.w, 0.f);
    ((float4*)out)[(size_t)graph * NN * 32 + i] = v;
}

// ---------------- driver ----------------------------------------------------
extern "C" void kernel_launch(void* const* d_in, const int* in_sizes, int n_in,
                              void* d_out, int out_size) {
    const float* x1  = (const float*)d_in[0];
    const int*   ei1 = (const int*)d_in[1];
    const int*   et1 = (const int*)d_in[2];
    const float* x2  = (const float*)d_in[3];
    const int*   ei2 = (const int*)d_in[4];
    const int*   et2 = (const int*)d_in[5];
    const float* W1  = (const float*)d_in[6];
    const float* q1  = (const float*)d_in[7];
    const float* k1  = (const float*)d_in[8];
    const float* b1  = (const float*)d_in[9];
    const float* W2  = (const float*)d_in[10];
    const float* q2  = (const float*)d_in[11];
    const float* k2  = (const float*)d_in[12];
    const float* b2  = (const float*)d_in[13];
    float* out = (float*)d_out;

    zero_kernel<<<1024, 256>>>();
    wqwk_kernel<<<dim3((RR * HD) / 8, NG), 256>>>(W1, q1, k1, W2, q2, k2);
    table_kernel<<<dim3((NN + 7) / 8, NG), 256>>>(x1, x2);
    xt_gemm<<<dim3(MBLK, RR, NG), 256>>>(x1, x2, W1, W2);
    edge_kernel<<<dim3(EE / 8, NG), 256>>>(ei1, et1, ei2, et2);
    epilogue_kernel<<<dim3((NN * 32 + 255) / 256, NG), 256>>>(b1, b2, out);
}